// round 1
// baseline (speedup 1.0000x reference)
#include <cuda_runtime.h>
#include <math.h>

#define SR_F        48000.0f
#define SOUND_SPEED 343.0f
#define MAX_ORDER   10
#define RIR_LEN     24000
#define BETA_F      0.9f
#define TAPS        81
#define HALF        40
#define AXN         42            // axis-image table size (2*(2*10+1))
#define IMGS        (AXN*AXN*AXN) // 74088

// ---------------------------------------------------------------------------
// Kernel 1: zero the RIR region of d_out and write origin[b].
// d_out layout: [B * RIR_LEN floats rir][B floats origin]
// ---------------------------------------------------------------------------
__global__ void init_kernel(const float* __restrict__ in, float* __restrict__ out, int B)
{
    int i = blockIdx.x * blockDim.x + threadIdx.x;
    int total = B * RIR_LEN;
    if (i < total) out[i] = 0.0f;
    if (i < B) {
        const float* row = in + i * 9;
        float rx = row[0] * 10.0f, ry = row[1] * 10.0f, rz = row[2] * 10.0f;
        float mx = row[3] * rx,    my = row[4] * ry,    mz = row[5] * rz;
        float sx = row[6] * rx,    sy = row[7] * ry,    sz = row[8] * rz;
        float dx = mx - sx, dy = my - sy, dz = mz - sz;
        float nrm = sqrtf(dx * dx + dy * dy + dz * dz);
        out[total + i] = 40.0f + SR_F * nrm / SOUND_SPEED;
    }
}

// Decode axis-image table entry a in [0, 42):
//   p = a >= 21 ? 1 : 0 ; n = (a - 21*p) - 10
//   sign = 1 - 2p ; off = 2n ; order = |n - p| + |n|
__device__ __forceinline__ void decode_axis(int a, float& sign, float& off, int& order)
{
    int p = (a >= 21) ? 1 : 0;
    int n = a - 21 * p - 10;
    sign  = (float)(1 - 2 * p);
    off   = (float)(2 * n);
    order = abs(n - p) + abs(n);
}

// ---------------------------------------------------------------------------
// Kernel 2: one thread per (batch, image). Valid images (tot_order<=10 and
// delay inside the RIR window) scatter an 81-tap windowed sinc.
// ---------------------------------------------------------------------------
__global__ void rir_kernel(const float* __restrict__ in, float* __restrict__ out, int B)
{
    long long tid = (long long)blockIdx.x * blockDim.x + threadIdx.x;
    if (tid >= (long long)B * IMGS) return;

    int b = (int)(tid / IMGS);
    int r = (int)(tid % IMGS);
    int ax = r / (AXN * AXN);
    int ay = (r / AXN) % AXN;
    int az = r % AXN;

    float sgx, ofx; int ox; decode_axis(ax, sgx, ofx, ox);
    float sgy, ofy; int oy; decode_axis(ay, sgy, ofy, oy);
    float sgz, ofz; int oz; decode_axis(az, sgz, ofz, oz);

    int tot = ox + oy + oz;
    if (tot > MAX_ORDER) return;

    const float* row = in + b * 9;
    float rx = row[0] * 10.0f, ry = row[1] * 10.0f, rz = row[2] * 10.0f;
    float mx = row[3] * rx,    my = row[4] * ry,    mz = row[5] * rz;
    float sx = row[6] * rx,    sy = row[7] * ry,    sz = row[8] * rz;

    float dx = sgx * sx + ofx * rx - mx;
    float dy = sgy * sy + ofy * ry - my;
    float dz = sgz * sz + ofz * rz - mz;

    float dist = sqrtf(dx * dx + dy * dy + dz * dz);
    float tau  = SR_F * dist / SOUND_SPEED;
    float i0   = floorf(tau);
    float frac = tau - i0;

    int base = (int)i0 + HALF;          // first tap index (ki = 0)
    if (base >= RIR_LEN) return;        // entire 81-tap window out of range

    // beta^tot (tot <= 10) — exact repeated multiply
    float bp = 1.0f;
    #pragma unroll
    for (int k = 0; k < MAX_ORDER; ++k)
        bp = (k < tot) ? bp * BETA_F : bp;

    float amp = bp / (4.0f * 3.14159265358979323846f * dist);

    float* rir = out + (long long)b * RIR_LEN;

    #pragma unroll 4
    for (int ki = 0; ki < TAPS; ++ki) {
        int idx = base + ki;
        if (idx >= RIR_LEN) break;      // idx >= 0 always (base >= HALF >= 0)
        float t  = (float)(ki - HALF) - frac;
        float at = fabsf(t);
        if (at > (float)HALF) continue; // Hann window support
        float win = 0.5f * (1.0f + cospif(t * (1.0f / (HALF + 1))));
        float s;
        if (t == 0.0f) {
            s = 1.0f;
        } else {
            s = sinpif(t) / (3.14159265358979323846f * t);
        }
        atomicAdd(&rir[idx], amp * s * win);
    }
}

extern "C" void kernel_launch(void* const* d_in, const int* in_sizes, int n_in,
                              void* d_out, int out_size)
{
    const float* in = (const float*)d_in[0];
    float* out = (float*)d_out;
    int B = in_sizes[0] / 9;

    int initN = B * RIR_LEN;            // origin writes covered (B <= initN)
    init_kernel<<<(initN + 255) / 256, 256>>>(in, out, B);

    long long total = (long long)B * IMGS;
    int blocks = (int)((total + 255) / 256);
    rir_kernel<<<blocks, 256>>>(in, out, B);
}

// round 2
// speedup vs baseline: 3.2476x; 3.2476x over previous
#include <cuda_runtime.h>
#include <math.h>

#define SR_F        48000.0f
#define SOUND_SPEED 343.0f
#define MAX_ORDER   10
#define RIR_LEN     24000
#define TAPS        81
#define HALF        40
#define AXN         42            // axis-image table size (2*(2*10+1))
#define IMGS        (AXN*AXN*AXN) // 74088
#define NVALID      1561          // #(o1,o2,o3) triples with tot_order <= 10 (exact)
#define MAXB        16

// Per-(batch,image) record, 32B for two float4 loads.
struct Rec {
    int   base;   // floor(tau) + HALF  (>= HALF); RIR_LEN if out of range
    float frac;   // tau - floor(tau)
    float amp;    // beta^tot / (4*pi*dist)
    float c;      // amp * sin(pi*frac) / pi
    float cw;     // cos(pi*(40+frac)/41)
    float sw;     // sin(pi*(40+frac)/41)
    float p0, p1;
};

__device__ Rec   g_rec[MAXB * NVALID];
__device__ float g_ct[TAPS];   // cos(pi*k/41)
__device__ float g_st[TAPS];   // sin(pi*k/41)
__device__ int   g_cnt;

__constant__ float BETA_POW[11] = {
    1.0f, 0.9f, 0.81f, 0.729f, 0.6561f, 0.59049f,
    0.531441f, 0.4782969f, 0.43046721f, 0.387420489f, 0.3486784401f
};

// ---------------------------------------------------------------------------
// Kernel 1: zero RIR, write origin, build per-tap cos/sin table, reset counter.
// d_out layout: [B*RIR_LEN floats rir][B floats origin]
// ---------------------------------------------------------------------------
__global__ void init_kernel(const float* __restrict__ in, float* __restrict__ out, int B)
{
    int i = blockIdx.x * blockDim.x + threadIdx.x;
    int total = B * RIR_LEN;
    if (i < total) out[i] = 0.0f;
    if (i < TAPS) {
        float a = (float)i * (1.0f / 41.0f);
        g_ct[i] = cospif(a);
        g_st[i] = sinpif(a);
    }
    if (i == 0) g_cnt = 0;
    if (i < B) {
        const float* row = in + i * 9;
        float rx = row[0] * 10.0f, ry = row[1] * 10.0f, rz = row[2] * 10.0f;
        float dx = row[3] * rx - row[6] * rx;
        float dy = row[4] * ry - row[7] * ry;
        float dz = row[5] * rz - row[8] * rz;
        float nrm = sqrtf(dx * dx + dy * dy + dz * dz);
        out[total + i] = 40.0f + SR_F * nrm / SOUND_SPEED;
    }
}

// Decode axis-image table entry a in [0,42):
//   p = a>=21, n = a-21p-10 ; sign=1-2p ; off=2n ; order=|n-p|+|n|
__device__ __forceinline__ void decode_axis(int a, float& sign, float& off, int& order)
{
    int p = (a >= 21) ? 1 : 0;
    int n = a - 21 * p - 10;
    sign  = (float)(1 - 2 * p);
    off   = (float)(2 * n);
    order = abs(n - p) + abs(n);
}

// ---------------------------------------------------------------------------
// Kernel 2: scan 74088 batch-independent triples, compact valid ones, and
// emit one 32B record per (batch, valid-image).
// ---------------------------------------------------------------------------
__global__ void build_kernel(const float* __restrict__ in, int B)
{
    int img = blockIdx.x * blockDim.x + threadIdx.x;
    if (img >= IMGS) return;

    int ax = img / (AXN * AXN);
    int ay = (img / AXN) % AXN;
    int az = img % AXN;

    float sgx, ofx; int ox; decode_axis(ax, sgx, ofx, ox);
    float sgy, ofy; int oy; decode_axis(ay, sgy, ofy, oy);
    float sgz, ofz; int oz; decode_axis(az, sgz, ofz, oz);

    int tot = ox + oy + oz;
    if (tot > MAX_ORDER) return;

    int s = atomicAdd(&g_cnt, 1);     // slot in [0, NVALID)
    float bp = BETA_POW[tot];
    const float INV_PI = 0.318309886183790672f;

    for (int b = 0; b < B; ++b) {
        const float* row = in + b * 9;
        float rx = row[0] * 10.0f, ry = row[1] * 10.0f, rz = row[2] * 10.0f;
        float mx = row[3] * rx,    my = row[4] * ry,    mz = row[5] * rz;
        float sx = row[6] * rx,    sy = row[7] * ry,    sz = row[8] * rz;

        float dx = sgx * sx + ofx * rx - mx;
        float dy = sgy * sy + ofy * ry - my;
        float dz = sgz * sz + ofz * rz - mz;

        float dist = sqrtf(dx * dx + dy * dy + dz * dz);
        float tau  = SR_F * dist / SOUND_SPEED;
        float i0   = floorf(tau);
        float frac = tau - i0;

        Rec r;
        r.base = (int)i0 + HALF;
        r.amp  = bp / (4.0f * 3.14159265358979323846f * dist);
        if (r.base >= RIR_LEN) { r.base = RIR_LEN; r.amp = 0.0f; }
        r.frac = frac;
        r.c    = r.amp * sinpif(frac) * INV_PI;
        float bb = (40.0f + frac) * (1.0f / 41.0f);
        r.cw   = cospif(bb);
        r.sw   = sinpif(bb);
        r.p0 = 0.0f; r.p1 = 0.0f;
        g_rec[b * NVALID + s] = r;
    }
}

// ---------------------------------------------------------------------------
// Kernel 3: one thread per (record, tap). ~1.01M uniform threads.
//   sinc(t)*amp = -(-1)^tap * c / t  (t != 0),  amp (t == 0)
//   win = 0.5*(1 + ct[tap]*cw + st[tap]*sw)
// ---------------------------------------------------------------------------
__global__ void tap_kernel(float* __restrict__ out, int total)
{
    int tid = blockIdx.x * blockDim.x + threadIdx.x;
    if (tid >= total) return;

    int rec = tid / TAPS;
    int tap = tid - rec * TAPS;

    const float4* rp = (const float4*)&g_rec[rec];
    float4 r0 = __ldg(rp + 0);
    float4 r1 = __ldg(rp + 1);
    int   base = __float_as_int(r0.x);
    float frac = r0.y;
    float amp  = r0.z;
    float c    = r0.w;
    float cw   = r1.x;
    float sw   = r1.y;

    int idx = base + tap;
    if (idx >= RIR_LEN) return;
    if (tap == 0 && frac > 0.0f) return;   // |t| > HALF -> window = 0

    float t = (float)(tap - HALF) - frac;
    float sincamp;
    if (t == 0.0f) {
        sincamp = amp;                     // tap==40 && frac==0
    } else {
        float cs = (tap & 1) ? c : -c;
        sincamp = __fdividef(cs, t);
    }

    float win = 0.5f * (1.0f + fmaf(g_ct[tap], cw, g_st[tap] * sw));

    int b = rec / NVALID;
    atomicAdd(out + b * RIR_LEN + idx, sincamp * win);
}

extern "C" void kernel_launch(void* const* d_in, const int* in_sizes, int n_in,
                              void* d_out, int out_size)
{
    const float* in = (const float*)d_in[0];
    float* out = (float*)d_out;
    int B = in_sizes[0] / 9;
    if (B > MAXB) B = MAXB;

    int initN = B * RIR_LEN;
    init_kernel<<<(initN + 255) / 256, 256>>>(in, out, B);

    build_kernel<<<(IMGS + 255) / 256, 256>>>(in, B);

    int total = B * NVALID * TAPS;
    tap_kernel<<<(total + 255) / 256, 256>>>(out, total);
}

// round 3
// speedup vs baseline: 4.8290x; 1.4870x over previous
#include <cuda_runtime.h>
#include <math.h>

#define SR_F        48000.0f
#define SOUND_SPEED 343.0f
#define MAX_ORDER   10
#define RIR_LEN     24000
#define TAPS        81
#define HALF        40
#define AXN         42            // axis-image table size (2*(2*10+1))
#define IMGS        (AXN*AXN*AXN) // 74088
#define NVALID      1561          // #(ax,ay,az) triples with tot_order <= 10 (exact)
#define MAXB        16

// ---------------------------------------------------------------------------
// Compile-time table of valid axis-index triples (tot_order <= MAX_ORDER),
// packed as ax + 42*ay + 42*42*az. Batch-independent.
// ---------------------------------------------------------------------------
constexpr int axis_order_ct(int a) {
    int p = (a >= 21) ? 1 : 0;
    int n = a - 21 * p - 10;
    int o1 = n - p; if (o1 < 0) o1 = -o1;
    int o2 = n;     if (o2 < 0) o2 = -o2;
    return o1 + o2;
}

struct ValidTable {
    int v[NVALID];
    constexpr ValidTable() : v() {
        int ord[AXN] = {};
        for (int a = 0; a < AXN; ++a) ord[a] = axis_order_ct(a);
        int s = 0;
        for (int az = 0; az < AXN; ++az)
            for (int ay = 0; ay < AXN; ++ay)
                for (int ax = 0; ax < AXN; ++ax)
                    if (ord[ax] + ord[ay] + ord[az] <= MAX_ORDER)
                        v[s++] = ax + AXN * ay + AXN * AXN * az;
    }
};

__device__ const ValidTable VT = ValidTable();

// Per-(batch,image) record, 32B = two float4 loads.
struct Rec {
    int   base_g; // b*RIR_LEN + floor(tau) + HALF (clamped to end_g if OOR)
    float frac;   // tau - floor(tau)
    float amp;    // beta^tot / (4*pi*dist)
    float c;      // amp * sin(pi*frac) / pi
    float cw;     // cos(pi*(40+frac)/41)
    float sw;     // sin(pi*(40+frac)/41)
    int   end_g;  // (b+1)*RIR_LEN
    float pad;
};

__device__ Rec   g_rec[MAXB * NVALID];
__device__ float g_ct[TAPS];   // cos(pi*k/41)
__device__ float g_st[TAPS];   // sin(pi*k/41)

__constant__ float BETA_POW[11] = {
    1.0f, 0.9f, 0.81f, 0.729f, 0.6561f, 0.59049f,
    0.531441f, 0.4782969f, 0.43046721f, 0.387420489f, 0.3486784401f
};

__device__ __forceinline__ void decode_axis(int a, float& sign, float& off, int& order)
{
    int p = (a >= 21) ? 1 : 0;
    int n = a - 21 * p - 10;
    sign  = (float)(1 - 2 * p);
    off   = (float)(2 * n);
    order = abs(n - p) + abs(n);
}

// ---------------------------------------------------------------------------
// Kernel A: zero RIR (float4), build all records from the compile-time table,
// build tap cos/sin tables, write origin.
// d_out layout: [B*RIR_LEN floats rir][B floats origin]
// ---------------------------------------------------------------------------
__global__ void prep_kernel(const float* __restrict__ in, float* __restrict__ out,
                            int B, int zeroN4, int nrec)
{
    int i = blockIdx.x * blockDim.x + threadIdx.x;

    if (i < zeroN4)
        ((float4*)out)[i] = make_float4(0.f, 0.f, 0.f, 0.f);

    if (i < TAPS) {
        float a = (float)i * (1.0f / 41.0f);
        g_ct[i] = cospif(a);
        g_st[i] = sinpif(a);
    }

    if (i < B) {
        const float* row = in + i * 9;
        float rx = row[0] * 10.0f, ry = row[1] * 10.0f, rz = row[2] * 10.0f;
        float dx = (row[3] - row[6]) * rx;
        float dy = (row[4] - row[7]) * ry;
        float dz = (row[5] - row[8]) * rz;
        float nrm = sqrtf(dx * dx + dy * dy + dz * dz);
        out[B * RIR_LEN + i] = 40.0f + SR_F * nrm / SOUND_SPEED;
    }

    if (i < nrec) {
        int b = i / NVALID;
        int s = i - b * NVALID;
        int img = __ldg(&VT.v[s]);

        int ax = img % AXN;
        int ay = (img / AXN) % AXN;
        int az = img / (AXN * AXN);

        float sgx, ofx; int ox; decode_axis(ax, sgx, ofx, ox);
        float sgy, ofy; int oy; decode_axis(ay, sgy, ofy, oy);
        float sgz, ofz; int oz; decode_axis(az, sgz, ofz, oz);

        const float* row = in + b * 9;
        float rx = row[0] * 10.0f, ry = row[1] * 10.0f, rz = row[2] * 10.0f;
        float mx = row[3] * rx,    my = row[4] * ry,    mz = row[5] * rz;
        float sx = row[6] * rx,    sy = row[7] * ry,    sz = row[8] * rz;

        float dx = sgx * sx + ofx * rx - mx;
        float dy = sgy * sy + ofy * ry - my;
        float dz = sgz * sz + ofz * rz - mz;

        float dist = sqrtf(dx * dx + dy * dy + dz * dz);
        float tau  = SR_F * dist / SOUND_SPEED;
        float i0   = floorf(tau);
        float frac = tau - i0;

        const float INV_PI = 0.318309886183790672f;
        Rec r;
        int base  = (int)i0 + HALF;
        int bofs  = b * RIR_LEN;
        r.end_g   = bofs + RIR_LEN;
        r.amp     = BETA_POW[ox + oy + oz] / (4.0f * 3.14159265358979323846f * dist);
        r.base_g  = (base >= RIR_LEN) ? r.end_g : bofs + base;
        r.frac    = frac;
        r.c       = r.amp * sinpif(frac) * INV_PI;
        float bb  = (40.0f + frac) * (1.0f / 41.0f);
        r.cw      = cospif(bb);
        r.sw      = sinpif(bb);
        r.pad     = 0.0f;
        g_rec[i]  = r;
    }
}

// ---------------------------------------------------------------------------
// Kernel B: one warp per record; lane handles taps {lane, lane+32, lane+64}.
//   sinc(t)*amp = sign(tap)*c / t (t != 0),  amp (t == 0)
//   win = 0.5*(1 + ct[tap]*cw + st[tap]*sw)
// ---------------------------------------------------------------------------
__global__ void tap_kernel(float* __restrict__ out, int nrec)
{
    int w    = (blockIdx.x * blockDim.x + threadIdx.x) >> 5;
    int lane = threadIdx.x & 31;
    if (w >= nrec) return;

    const float4* rp = (const float4*)&g_rec[w];
    float4 r0 = __ldg(rp + 0);       // broadcast: all lanes same address
    float4 r1 = __ldg(rp + 1);
    int   base_g = __float_as_int(r0.x);
    float frac   = r0.y;
    float amp    = r0.z;
    float c      = r0.w;
    float cw     = r1.x;
    float sw     = r1.y;
    int   end_g  = __float_as_int(r1.z);

    #pragma unroll
    for (int k = 0; k < 3; ++k) {
        int tap = lane + 32 * k;
        if (tap >= TAPS) break;
        int idx = base_g + tap;
        if (idx >= end_g) break;                 // taps only grow
        if (tap == 0 && frac > 0.0f) continue;   // |t| > HALF -> window = 0

        float t = (float)(tap - HALF) - frac;
        float sincamp;
        if (t == 0.0f) {
            sincamp = amp;                       // tap==40 && frac==0
        } else {
            float cs = (tap & 1) ? c : -c;
            sincamp = __fdividef(cs, t);
        }
        float win = 0.5f * (1.0f + fmaf(__ldg(&g_ct[tap]), cw,
                                        __ldg(&g_st[tap]) * sw));
        atomicAdd(out + idx, sincamp * win);
    }
}

extern "C" void kernel_launch(void* const* d_in, const int* in_sizes, int n_in,
                              void* d_out, int out_size)
{
    const float* in = (const float*)d_in[0];
    float* out = (float*)d_out;
    int B = in_sizes[0] / 9;
    if (B > MAXB) B = MAXB;

    int nrec   = B * NVALID;
    int zeroN4 = B * (RIR_LEN / 4);              // float4 count (RIR_LEN % 4 == 0)
    int threadsA = zeroN4;                        // zeroN4 >= nrec, TAPS, B always
    prep_kernel<<<(threadsA + 255) / 256, 256>>>(in, out, B, zeroN4, nrec);

    int threadsB = nrec * 32;                     // one warp per record
    tap_kernel<<<(threadsB + 255) / 256, 256>>>(out, nrec);
}